// round 9
// baseline (speedup 1.0000x reference)
#include <cuda_runtime.h>
#include <cuda_bf16.h>
#include <float.h>
#include <math.h>
#include <stdint.h>

// Problem constants
#define N_TOK   32768
#define DIM     512
#define NTYPE   26
#define PER     128
#define NCODE   (NTYPE*PER)     // 3328
#define SAMP    312
#define ND      (N_TOK*DIM)
#define TEMP    0.07f
#define COMMIT  0.25f
#define KCH     64              // bf16 k-chunk: 64*2B = 128B row
#define NCH     (DIM/KCH)       // 8
#define MARGIN  2.5e-4f         // ~25x worst-case bf16-split score error

// -------- scratch --------
__device__ float         g_ne[NCODE*DIM];
__device__ __nv_bfloat16 g_ehi[NCODE*DIM];
__device__ __nv_bfloat16 g_elo[NCODE*DIM];
__device__ float         g_en2[NCODE];
__device__ int    g_count[NTYPE];
__device__ int    g_offset[NTYPE];
__device__ int    g_cursor[NTYPE];
__device__ int    g_order[N_TOK];
__device__ int    g_work[512];
__device__ int    g_nwork;
__device__ int    g_ticket;
__device__ int    g_udone;
__device__ int    g_hist_done;
__device__ float  g_se[SAMP*DIM];
__device__ int    g_slab[SAMP];
__device__ double g_diff_acc;
__device__ double g_uloss_acc;

// -------- helpers --------
__device__ __forceinline__ uint32_t smem_u32(const void* p) {
    uint32_t a;
    asm("{ .reg .u64 t; cvta.to.shared.u64 t, %1; cvt.u32.u64 %0, t; }" : "=r"(a) : "l"(p));
    return a;
}
__device__ __forceinline__ uint32_t sw128(uint32_t off) {
    return off ^ ((off >> 3) & 0x70);
}
#define LDSM4(r, addr) \
    asm volatile("ldmatrix.sync.aligned.m8n8.x4.shared.b16 {%0,%1,%2,%3}, [%4];" \
        : "=r"((r)[0]), "=r"((r)[1]), "=r"((r)[2]), "=r"((r)[3]) : "r"(addr))
#define MMA16816(d, a, b0, b1) \
    asm volatile("mma.sync.aligned.m16n8k16.row.col.f32.bf16.bf16.f32 " \
        "{%0,%1,%2,%3},{%4,%5,%6,%7},{%8,%9},{%0,%1,%2,%3};" \
        : "+f"((d)[0]), "+f"((d)[1]), "+f"((d)[2]), "+f"((d)[3]) \
        : "r"((a)[0]), "r"((a)[1]), "r"((a)[2]), "r"((a)[3]), "r"(b0), "r"(b1))

// -------- kernels --------
__global__ void k_init() {
    int t = threadIdx.x;
    if (t < NTYPE) g_count[t] = 0;
    if (t == 0) {
        g_diff_acc = 0.0; g_uloss_acc = 0.0;
        g_ticket = 0; g_udone = 0; g_hist_done = 0;
    }
}

// block per code row: norm2, normalized row, bf16 hi/lo split of RAW emb
__global__ void k_norm_emb(const float* __restrict__ emb) {
    int row = blockIdx.x;
    int t = threadIdx.x;
    float4 a = ((const float4*)(emb + (size_t)row * DIM))[t];
    float s = a.x*a.x + a.y*a.y + a.z*a.z + a.w*a.w;
    #pragma unroll
    for (int o = 16; o; o >>= 1) s += __shfl_xor_sync(0xffffffffu, s, o);
    __shared__ float ws[4];
    if ((t & 31) == 0) ws[t >> 5] = s;
    __syncthreads();
    float tot = ws[0] + ws[1] + ws[2] + ws[3];
    if (t == 0) g_en2[row] = tot;
    float inv = 1.0f / fmaxf(sqrtf(tot), 1e-12f);
    ((float4*)(g_ne + (size_t)row * DIM))[t] =
        make_float4(a.x*inv, a.y*inv, a.z*inv, a.w*inv);
    float v[4] = {a.x, a.y, a.z, a.w};
    __nv_bfloat16 hi[4], lo[4];
    #pragma unroll
    for (int e = 0; e < 4; e++) {
        hi[e] = __float2bfloat16(v[e]);
        lo[e] = __float2bfloat16(v[e] - __bfloat162float(hi[e]));
    }
    *(uint2*)(g_ehi + (size_t)row * DIM + 4*t) = *(const uint2*)hi;
    *(uint2*)(g_elo + (size_t)row * DIM + 4*t) = *(const uint2*)lo;
}

// hist + (last block) fused scan/worklist
__global__ void k_hist(const int* __restrict__ Q) {
    __shared__ int h[NTYPE];
    __shared__ int lastflag;
    int tid = threadIdx.x;
    if (tid < NTYPE) h[tid] = 0;
    __syncthreads();
    for (int i = blockIdx.x * blockDim.x + tid; i < N_TOK; i += gridDim.x * blockDim.x)
        atomicAdd(&h[Q[i]], 1);
    __syncthreads();
    if (tid < NTYPE && h[tid]) atomicAdd(&g_count[tid], h[tid]);
    __threadfence();
    if (tid == 0) lastflag = (atomicAdd(&g_hist_done, 1) == (int)gridDim.x - 1);
    __syncthreads();
    if (lastflag && tid < 32) {
        int lane = tid;
        int c = (lane < NTYPE) ? g_count[lane] : 0;
        int tiles = (c + 127) / 128;
        int sc = c, st = tiles;
        #pragma unroll
        for (int o = 1; o < 32; o <<= 1) {
            int v = __shfl_up_sync(0xffffffffu, sc, o);
            int w = __shfl_up_sync(0xffffffffu, st, o);
            if (lane >= o) { sc += v; st += w; }
        }
        int off = sc - c, toff = st - tiles;
        if (lane < NTYPE) {
            g_offset[lane] = off;
            g_cursor[lane] = off;
            for (int t2 = 0; t2 < tiles; t2++) g_work[toff + t2] = (lane << 8) | t2;
        }
        int tot = __shfl_sync(0xffffffffu, st, NTYPE - 1);
        if (lane == 0) g_nwork = tot;
    }
}

__global__ void k_scatter(const int* __restrict__ Q) {
    __shared__ int loc[NTYPE], base[NTYPE];
    int tid = threadIdx.x;
    if (tid < NTYPE) loc[tid] = 0;
    __syncthreads();
    int per = (N_TOK + gridDim.x - 1) / gridDim.x;
    int s = blockIdx.x * per;
    int e = min(s + per, N_TOK);
    for (int i = s + tid; i < e; i += blockDim.x)
        atomicAdd(&loc[Q[i]], 1);
    __syncthreads();
    if (tid < NTYPE) { base[tid] = atomicAdd(&g_cursor[tid], loc[tid]); loc[tid] = 0; }
    __syncthreads();
    for (int i = s + tid; i < e; i += blockDim.x) {
        int t = Q[i];
        g_order[base[t] + atomicAdd(&loc[t], 1)] = i;
    }
}

// Persistent warp-MMA bf16-split GEMM + argmin (+exact rescan) + loss + copy.
// Dynamic smem: Ahi(16K) Alo(16K) Bhi(16K) Blo(16K) = 64KB.
__global__ __launch_bounds__(256, 1) void k_argmin(const float* __restrict__ x,
                                                   const float* __restrict__ emb,
                                                   float* __restrict__ out) {
    extern __shared__ __align__(1024) char dyn[];
    char* sAhi = dyn;
    char* sAlo = dyn + 16384;
    char* sBhi = dyn + 32768;
    char* sBlo = dyn + 49152;

    __shared__ int   toks[128];
    __shared__ float snorm[128];
    __shared__ float sen2[128];
    __shared__ int   scodes[128];
    __shared__ float s_best[2][128];
    __shared__ float s_sec[2][128];
    __shared__ int   s_bc[2][128];
    __shared__ float s_fbest[128];
    __shared__ int   s_fbc[128];
    __shared__ int   s_work;
    __shared__ float red[256];

    int tid  = threadIdx.x;
    int lane = tid & 31;
    int warp = tid >> 5;
    int wm = warp >> 1;          // 0..3: m-band (32 rows)
    int wn = warp & 1;           // 0..1: n-band (64 cols)
    int fr = tid >> 1;           // fill row 0..127
    int fq = tid & 1;            // fill k-half (32 bf16)
    float local_loss = 0.0f;

    // ldmatrix lane address components
    int rA = (lane & 7) + ((lane >> 3) & 1) * 8;
    int kA = (lane >> 4) * 16;
    int rB = (lane & 7) + (lane >> 4) * 8;
    int kB = ((lane >> 3) & 1) * 16;
    uint32_t aHi = smem_u32(sAhi), aLo = smem_u32(sAlo);
    uint32_t bHi = smem_u32(sBhi), bLo = smem_u32(sBlo);

    for (;;) {
        if (tid == 0) s_work = atomicAdd(&g_ticket, 1);
        __syncthreads();
        int w = s_work;
        if (w >= g_nwork) break;
        int wk   = g_work[w];
        int type = wk >> 8;
        int row0 = (wk & 255) * 128;
        int cnt  = g_count[type];
        int rows = min(128, cnt - row0);
        int code0 = type * PER;

        if (tid < 128) {
            int r = (tid < rows) ? tid : (rows - 1);
            toks[tid]  = g_order[g_offset[type] + row0 + r];
            snorm[tid] = 0.0f;
            sen2[tid]  = g_en2[code0 + tid];
        }
        __syncthreads();

        const float* xrow = x + (size_t)toks[fr] * DIM;
        const __nv_bfloat16* bhirow = g_ehi + (size_t)(code0 + fr) * DIM;
        const __nv_bfloat16* blorow = g_elo + (size_t)(code0 + fr) * DIM;

        float acc[2][8][4];
        #pragma unroll
        for (int i = 0; i < 2; i++)
            #pragma unroll
            for (int j = 0; j < 8; j++)
                #pragma unroll
                for (int q = 0; q < 4; q++) acc[i][j][q] = 0.0f;

        for (int ch = 0; ch < NCH; ch++) {
            // ---- fill A hi/lo (from x, converted) + sumsq ----
            int cbase = ch * KCH + fq * 32;
            float ps = 0.0f;
            #pragma unroll
            for (int u = 0; u < 4; u++) {
                float4 v0 = *(const float4*)(xrow + cbase + 8*u);
                float4 v1 = *(const float4*)(xrow + cbase + 8*u + 4);
                ps += v0.x*v0.x + v0.y*v0.y + v0.z*v0.z + v0.w*v0.w;
                ps += v1.x*v1.x + v1.y*v1.y + v1.z*v1.z + v1.w*v1.w;
                float f[8] = {v0.x,v0.y,v0.z,v0.w,v1.x,v1.y,v1.z,v1.w};
                __nv_bfloat16 hb[8], lb[8];
                #pragma unroll
                for (int e = 0; e < 8; e++) {
                    hb[e] = __float2bfloat16(f[e]);
                    lb[e] = __float2bfloat16(f[e] - __bfloat162float(hb[e]));
                }
                uint32_t boff = sw128(fr * 128 + fq * 64 + u * 16);
                *(uint4*)(sAhi + boff) = *(const uint4*)hb;
                *(uint4*)(sAlo + boff) = *(const uint4*)lb;
            }
            atomicAdd(&snorm[fr], ps);
            // ---- fill B hi/lo (precomputed bf16) ----
            #pragma unroll
            for (int u = 0; u < 4; u++) {
                uint32_t boff = sw128(fr * 128 + fq * 64 + u * 16);
                *(uint4*)(sBhi + boff) = *(const uint4*)(bhirow + cbase + 8*u);
                *(uint4*)(sBlo + boff) = *(const uint4*)(blorow + cbase + 8*u);
            }
            __syncthreads();

            #pragma unroll
            for (int ks = 0; ks < 4; ks++) {
                uint32_t ao0 = sw128((uint32_t)((wm*32 +  0 + rA)*128 + ks*32 + kA));
                uint32_t ao1 = sw128((uint32_t)((wm*32 + 16 + rA)*128 + ks*32 + kA));
                uint32_t ah0[4], ah1[4], al0[4], al1[4];
                LDSM4(ah0, aHi + ao0); LDSM4(ah1, aHi + ao1);
                LDSM4(al0, aLo + ao0); LDSM4(al1, aLo + ao1);
                uint32_t bh[8][2], bl[8][2];
                #pragma unroll
                for (int p = 0; p < 4; p++) {
                    uint32_t bo = sw128((uint32_t)((wn*64 + p*16 + rB)*128 + ks*32 + kB));
                    uint32_t t4[4];
                    LDSM4(t4, bHi + bo);
                    bh[2*p][0] = t4[0]; bh[2*p][1] = t4[1];
                    bh[2*p+1][0] = t4[2]; bh[2*p+1][1] = t4[3];
                    LDSM4(t4, bLo + bo);
                    bl[2*p][0] = t4[0]; bl[2*p][1] = t4[1];
                    bl[2*p+1][0] = t4[2]; bl[2*p+1][1] = t4[3];
                }
                #pragma unroll
                for (int nf = 0; nf < 8; nf++) {
                    MMA16816(acc[0][nf], ah0, bh[nf][0], bh[nf][1]);
                    MMA16816(acc[0][nf], ah0, bl[nf][0], bl[nf][1]);
                    MMA16816(acc[0][nf], al0, bh[nf][0], bh[nf][1]);
                    MMA16816(acc[1][nf], ah1, bh[nf][0], bh[nf][1]);
                    MMA16816(acc[1][nf], ah1, bl[nf][0], bl[nf][1]);
                    MMA16816(acc[1][nf], al1, bh[nf][0], bh[nf][1]);
                }
            }
            __syncthreads();
        }

        // ---- stage 1: per-warp best/sec over its 64 cols ----
        #pragma unroll
        for (int mf = 0; mf < 2; mf++) {
            #pragma unroll
            for (int rr = 0; rr < 2; rr++) {
                int m = wm*32 + mf*16 + (lane >> 2) + rr*8;
                float invn = 1.0f / fmaxf(sqrtf(snorm[m]), 1e-12f);
                float best = FLT_MAX, sec = FLT_MAX; int bc = 1 << 30;
                #pragma unroll
                for (int nf = 0; nf < 8; nf++) {
                    int j = wn*64 + nf*8 + 2*(lane & 3);
                    float s0 = sen2[j]   - 2.0f*invn*acc[mf][nf][2*rr];
                    float s1 = sen2[j+1] - 2.0f*invn*acc[mf][nf][2*rr+1];
                    if (s0 < best || (s0 == best && j < bc)) { sec = best; best = s0; bc = j; }
                    else sec = fminf(sec, s0);
                    if (s1 < best || (s1 == best && j+1 < bc)) { sec = best; best = s1; bc = j+1; }
                    else sec = fminf(sec, s1);
                }
                #pragma unroll
                for (int o = 1; o <= 2; o <<= 1) {
                    float ob = __shfl_xor_sync(0xffffffffu, best, o);
                    int   oc = __shfl_xor_sync(0xffffffffu, bc, o);
                    float os = __shfl_xor_sync(0xffffffffu, sec, o);
                    if (ob < best || (ob == best && oc < bc)) {
                        sec = fminf(best, os); best = ob; bc = oc;
                    } else sec = fminf(sec, ob);
                }
                if ((lane & 3) == 0) {
                    s_best[wn][m] = best; s_bc[wn][m] = bc; s_sec[wn][m] = sec;
                }
            }
        }
        __syncthreads();

        // ---- stage 2: merge halves; exact rescan if ambiguous ----
        bool amb = false;
        if (tid < 128) {
            int m = tid;
            float b0 = s_best[0][m], b1 = s_best[1][m];
            int   c0i = s_bc[0][m],  c1i = s_bc[1][m];
            float sc0 = s_sec[0][m], sc1 = s_sec[1][m];
            float best, sec; int bc;
            if (b1 < b0 || (b1 == b0 && c1i < c0i)) {
                best = b1; bc = c1i; sec = fminf(b0, sc1);
            } else {
                best = b0; bc = c0i; sec = fminf(b1, sc0);
            }
            s_fbest[m] = best; s_fbc[m] = bc;
            amb = (m < rows) && (sec - best < MARGIN);
        }
        unsigned msk = __ballot_sync(0xffffffffu, amb);
        while (msk) {
            int b = __ffs(msk) - 1; msk &= msk - 1;
            int m2 = (tid & 96) + b;
            int tok = toks[m2];
            float invn = 1.0f / fmaxf(sqrtf(snorm[m2]), 1e-12f);
            const float* xr = x + (size_t)tok * DIM;
            const float* e0 = emb + (size_t)(code0 + lane     ) * DIM;
            const float* e1 = emb + (size_t)(code0 + lane + 32) * DIM;
            const float* e2 = emb + (size_t)(code0 + lane + 64) * DIM;
            const float* e3 = emb + (size_t)(code0 + lane + 96) * DIM;
            // strict k-sequential fmaf chains (replicates the validated
            // scalar-FFMA kernel's arithmetic exactly; no reassociation)
            float dd0 = 0.0f, dd1 = 0.0f, dd2 = 0.0f, dd3 = 0.0f;
            #pragma unroll 8
            for (int k = 0; k < DIM; k++) {
                float xv = xr[k];
                dd0 = fmaf(xv, e0[k], dd0);
                dd1 = fmaf(xv, e1[k], dd1);
                dd2 = fmaf(xv, e2[k], dd2);
                dd3 = fmaf(xv, e3[k], dd3);
            }
            float bb = FLT_MAX; int bcc = 1 << 30;
            float ds[4] = {dd0, dd1, dd2, dd3};
            #pragma unroll
            for (int q = 0; q < 4; q++) {
                int c = lane + 32*q;
                float s = sen2[c] - 2.0f*invn*ds[q];
                if (s < bb || (s == bb && c < bcc)) { bb = s; bcc = c; }
            }
            #pragma unroll
            for (int o = 16; o; o >>= 1) {
                float s2 = __shfl_xor_sync(0xffffffffu, bb, o);
                int   c2 = __shfl_xor_sync(0xffffffffu, bcc, o);
                if (s2 < bb || (s2 == bb && c2 < bcc)) { bb = s2; bcc = c2; }
            }
            if (lane == 0) { s_fbest[m2] = bb; s_fbc[m2] = bcc; }
        }
        __syncwarp();
        if (tid < 128 && tid < rows) {
            int m = tid;
            int bc = s_fbc[m];
            float best = s_fbest[m];
            int tok  = toks[m];
            int code = code0 + bc;
            scodes[m] = code;
            out[ND + 2 + tok] = (float)code;
            float e2v = sen2[bc];
            local_loss += 2.0f - (e2v - best) / sqrtf(e2v);
        }
        __syncthreads();

        // ---- fused finalize: out row = g_ne[code] ----
        if (fr < rows) {
            const float4* src = (const float4*)(g_ne + (size_t)scodes[fr] * DIM) + fq * 64;
            float4*       dst = (float4*)(out + (size_t)toks[fr] * DIM) + fq * 64;
            #pragma unroll 8
            for (int q = 0; q < 64; q++) dst[q] = src[q];
        }
        // loop-top __syncthreads orders copy before smem reuse
    }

    red[tid] = local_loss;
    __syncthreads();
    for (int s = 128; s; s >>= 1) {
        if (tid < s) red[tid] += red[tid + s];
        __syncthreads();
    }
    if (tid == 0 && red[0] != 0.0f) atomicAdd(&g_diff_acc, (double)red[0]);
}

__global__ void k_gather_se(const int* __restrict__ samp) {
    int b = blockIdx.x;
    int s = samp[b];
    int t = threadIdx.x;
    ((float4*)(g_se + (size_t)b * DIM))[t] =
        ((const float4*)(g_ne + (size_t)s * DIM))[t];
    if (t == 0) g_slab[b] = s / PER;
}

__global__ __launch_bounds__(256) void k_uloss(float* __restrict__ out) {
    int i = blockIdx.x;
    __shared__ float si[DIM];
    __shared__ float wsum[8], wpos[8];
    int tid = threadIdx.x;
    if (tid < 128) ((float4*)si)[tid] = ((const float4*)(g_se + (size_t)i * DIM))[tid];
    __syncthreads();
    int lab_i = g_slab[i];
    int w = tid >> 5, lane = tid & 31;
    float sum = 0.0f, pos = 0.0f;
    for (int j = w; j < SAMP; j += 8) {
        const float* vj = g_se + (size_t)j * DIM;
        float p = 0.0f;
        #pragma unroll 4
        for (int d = lane; d < DIM; d += 32) p = fmaf(si[d], vj[d], p);
        #pragma unroll
        for (int o = 16; o; o >>= 1) p += __shfl_xor_sync(0xffffffffu, p, o);
        if (lane == 0 && j != i) {
            float e = expf(p / TEMP);
            sum += e;
            if (g_slab[j] == lab_i) pos += e;
        }
    }
    if (lane == 0) { wsum[w] = sum; wpos[w] = pos; }
    __syncthreads();
    if (tid == 0) {
        float S = 0.0f, P = 0.0f;
        #pragma unroll
        for (int k = 0; k < 8; k++) { S += wsum[k]; P += wpos[k]; }
        atomicAdd(&g_uloss_acc, (double)(-logf(P / S)));
        __threadfence();
        int d = atomicAdd(&g_udone, 1);
        if (d == SAMP - 1) {
            double u = atomicAdd(&g_uloss_acc, 0.0);
            out[ND]     = (float)((1.0 + (double)COMMIT) * g_diff_acc / (double)ND);
            out[ND + 1] = (float)(u / (double)SAMP);
        }
    }
}

// -------- launch --------
extern "C" void kernel_launch(void* const* d_in, const int* in_sizes, int n_in,
                              void* d_out, int out_size) {
    const float* x    = (const float*)d_in[0];
    const float* emb  = (const float*)d_in[1];
    const int*   Q    = (const int*)d_in[2];
    const int*   samp = (const int*)d_in[3];
    float* out = (float*)d_out;

    cudaFuncSetAttribute(k_argmin, cudaFuncAttributeMaxDynamicSharedMemorySize, 65536);

    k_init<<<1, 32>>>();
    k_norm_emb<<<NCODE, 128>>>(emb);
    k_hist<<<64, 256>>>(Q);
    k_scatter<<<64, 256>>>(Q);
    k_argmin<<<148, 256, 65536>>>(x, emb, out);
    k_gather_se<<<SAMP, 128>>>(samp);
    k_uloss<<<SAMP, 256>>>(out);
}

// round 10
// speedup vs baseline: 2.0584x; 2.0584x over previous
#include <cuda_runtime.h>
#include <float.h>
#include <math.h>
#include <stdint.h>

// Problem constants
#define N_TOK   32768
#define DIM     512
#define NTYPE   26
#define PER     128
#define NCODE   (NTYPE*PER)     // 3328
#define SAMP    312
#define ND      (N_TOK*DIM)     // 16777216
#define TEMP    0.07f
#define COMMIT  0.25f
#define KC      32

// -------- scratch (device globals; no allocation allowed) --------
__device__ float  g_ne[NCODE*DIM];     // normalized embeddings
__device__ float  g_en2[NCODE];        // ||emb_j||^2
__device__ int    g_count[NTYPE];
__device__ int    g_offset[NTYPE];
__device__ int    g_cursor[NTYPE];
__device__ int    g_order[N_TOK];
__device__ int    g_work[512];         // (type<<8)|tile worklist
__device__ int    g_nwork;
__device__ int    g_ticket;
__device__ int    g_udone;
__device__ int    g_hist_done;
__device__ double g_diff_acc;
__device__ double g_uloss_acc;

// -------- packed f32x2 helpers (validated in R4: exact same epilogue math) --------
__device__ __forceinline__ void ffma2(unsigned long long &d,
                                      unsigned long long a,
                                      unsigned long long b) {
    asm("fma.rn.f32x2 %0, %1, %2, %0;" : "+l"(d) : "l"(a), "l"(b));
}
__device__ __forceinline__ unsigned long long packdup(float v) {
    unsigned long long r;
    asm("mov.b64 %0, {%1, %1};" : "=l"(r) : "f"(v));
    return r;
}
__device__ __forceinline__ float f2lo(unsigned long long v) {
    return __uint_as_float((unsigned)(v & 0xffffffffull));
}
__device__ __forceinline__ float f2hi(unsigned long long v) {
    return __uint_as_float((unsigned)(v >> 32));
}

// -------- kernels --------
__global__ void k_init() {
    int t = threadIdx.x;
    if (t < NTYPE) g_count[t] = 0;
    if (t == 0) {
        g_diff_acc = 0.0; g_uloss_acc = 0.0;
        g_ticket = 0; g_udone = 0; g_hist_done = 0;
    }
}

// block per code row: norm2 + normalized row
__global__ void k_norm_emb(const float* __restrict__ emb) {
    int row = blockIdx.x;
    int t = threadIdx.x;
    float4 a = ((const float4*)(emb + (size_t)row * DIM))[t];
    float s = a.x*a.x + a.y*a.y + a.z*a.z + a.w*a.w;
    #pragma unroll
    for (int o = 16; o; o >>= 1) s += __shfl_xor_sync(0xffffffffu, s, o);
    __shared__ float ws[4];
    if ((t & 31) == 0) ws[t >> 5] = s;
    __syncthreads();
    float tot = ws[0] + ws[1] + ws[2] + ws[3];
    if (t == 0) g_en2[row] = tot;
    float inv = 1.0f / fmaxf(sqrtf(tot), 1e-12f);
    float4 o4 = make_float4(a.x*inv, a.y*inv, a.z*inv, a.w*inv);
    ((float4*)(g_ne + (size_t)row * DIM))[t] = o4;
}

// hist + (last block) fused scan/worklist  (validated in R9)
__global__ void k_hist(const int* __restrict__ Q) {
    __shared__ int h[NTYPE];
    __shared__ int lastflag;
    int tid = threadIdx.x;
    if (tid < NTYPE) h[tid] = 0;
    __syncthreads();
    for (int i = blockIdx.x * blockDim.x + tid; i < N_TOK; i += gridDim.x * blockDim.x)
        atomicAdd(&h[Q[i]], 1);
    __syncthreads();
    if (tid < NTYPE && h[tid]) atomicAdd(&g_count[tid], h[tid]);
    __threadfence();
    if (tid == 0) lastflag = (atomicAdd(&g_hist_done, 1) == (int)gridDim.x - 1);
    __syncthreads();
    if (lastflag && tid < 32) {
        int lane = tid;
        int c = (lane < NTYPE) ? g_count[lane] : 0;
        int tiles = (c + 127) / 128;
        int sc = c, st = tiles;
        #pragma unroll
        for (int o = 1; o < 32; o <<= 1) {
            int v = __shfl_up_sync(0xffffffffu, sc, o);
            int w = __shfl_up_sync(0xffffffffu, st, o);
            if (lane >= o) { sc += v; st += w; }
        }
        int off = sc - c, toff = st - tiles;
        if (lane < NTYPE) {
            g_offset[lane] = off;
            g_cursor[lane] = off;
            for (int t2 = 0; t2 < tiles; t2++) g_work[toff + t2] = (lane << 8) | t2;
        }
        int tot = __shfl_sync(0xffffffffu, st, NTYPE - 1);
        if (lane == 0) g_nwork = tot;
    }
}

__global__ void k_scatter(const int* __restrict__ Q) {
    __shared__ int loc[NTYPE], base[NTYPE];
    int tid = threadIdx.x;
    if (tid < NTYPE) loc[tid] = 0;
    __syncthreads();
    int per = (N_TOK + gridDim.x - 1) / gridDim.x;
    int s = blockIdx.x * per;
    int e = min(s + per, N_TOK);
    for (int i = s + tid; i < e; i += blockDim.x)
        atomicAdd(&loc[Q[i]], 1);
    __syncthreads();
    if (tid < NTYPE) { base[tid] = atomicAdd(&g_cursor[tid], loc[tid]); loc[tid] = 0; }
    __syncthreads();
    for (int i = s + tid; i < e; i += blockDim.x) {
        int t = Q[i];
        g_order[base[t] + atomicAdd(&loc[t], 1)] = i;
    }
}

// Persistent FFMA2 GEMM (register-duplicated A; same smem layout/volume as
// the proven scalar kernel) + fused row-norm + argmin + commit-loss
// + idx-tail + fused output-row copy (out row = g_ne[winning code]).
__global__ __launch_bounds__(256, 2) void k_argmin(const float* __restrict__ x,
                                                   const float* __restrict__ emb,
                                                   float* __restrict__ out) {
    __shared__ __align__(16) float As[KC][128];   // [k][token]
    __shared__ __align__(16) float Bs[KC][128];   // [k][code]
    __shared__ int   toks[128];
    __shared__ float snorm[128];
    __shared__ float sen2[128];
    __shared__ int   scodes[128];
    __shared__ int   s_work;
    __shared__ float red[256];

    int tid = threadIdx.x;
    int tx = tid & 15, ty = tid >> 4;   // 16x16 thread grid
    int fr = tid >> 1;                  // fill row 0..127
    int fq = tid & 1;                   // fill k-half (16 floats each)
    float local_loss = 0.0f;

    for (;;) {
        if (tid == 0) s_work = atomicAdd(&g_ticket, 1);
        __syncthreads();
        int w = s_work;
        if (w >= g_nwork) break;
        int wk   = g_work[w];
        int type = wk >> 8;
        int row0 = (wk & 255) * 128;
        int cnt  = g_count[type];
        int rows = min(128, cnt - row0);

        if (tid < 128) {
            int r = (tid < rows) ? tid : (rows - 1);
            toks[tid]  = g_order[g_offset[type] + row0 + r];
            snorm[tid] = 0.0f;
            sen2[tid]  = g_en2[type * PER + tid];
        }
        __syncthreads();

        const float* xrow = x   + (size_t)toks[fr] * DIM + fq * 16;
        const float* brow = emb + (size_t)(type * PER + fr) * DIM + fq * 16;

        unsigned long long acc[8][4];   // [row-frag][code-pair-group]
        #pragma unroll
        for (int i = 0; i < 8; i++)
            #pragma unroll
            for (int s = 0; s < 4; s++) acc[i][s] = 0ull;  // (0.f, 0.f)

        for (int k0 = 0; k0 < DIM; k0 += KC) {
            // --- fill A + accumulate row sumsq; fill B (identical to R5) ---
            float ps = 0.0f;
            #pragma unroll
            for (int u = 0; u < 4; u++) {
                float4 v = *(const float4*)(xrow + k0 + 4 * u);
                ps += v.x*v.x + v.y*v.y + v.z*v.z + v.w*v.w;
                int kb = fq * 16 + 4 * u;
                As[kb+0][fr] = v.x; As[kb+1][fr] = v.y;
                As[kb+2][fr] = v.z; As[kb+3][fr] = v.w;
            }
            atomicAdd(&snorm[fr], ps);
            #pragma unroll
            for (int u = 0; u < 4; u++) {
                float4 v = *(const float4*)(brow + k0 + 4 * u);
                int kb = fq * 16 + 4 * u;
                Bs[kb+0][fr] = v.x; Bs[kb+1][fr] = v.y;
                Bs[kb+2][fr] = v.z; Bs[kb+3][fr] = v.w;
            }
            __syncthreads();

            // --- FFMA2 inner: register-duplicated A, paired B ---
            #pragma unroll
            for (int kk = 0; kk < KC; kk++) {
                float4 a0 = *(const float4*)&As[kk][ty*4];
                float4 a1 = *(const float4*)&As[kk][64 + ty*4];
                unsigned long long av[8];
                av[0] = packdup(a0.x); av[1] = packdup(a0.y);
                av[2] = packdup(a0.z); av[3] = packdup(a0.w);
                av[4] = packdup(a1.x); av[5] = packdup(a1.y);
                av[6] = packdup(a1.z); av[7] = packdup(a1.w);
                const unsigned long long* Br =
                    (const unsigned long long*)&Bs[kk][0];   // 64 pairs per row
                unsigned long long bv[4];
                #pragma unroll
                for (int s = 0; s < 4; s++) bv[s] = Br[tx + 16*s];
                #pragma unroll
                for (int i = 0; i < 8; i++)
                    #pragma unroll
                    for (int s = 0; s < 4; s++)
                        ffma2(acc[i][s], av[i], bv[s]);
            }
            __syncthreads();
        }

        // --- epilogue: argmin + loss + idx tail (R4-validated pairing) ---
        #pragma unroll
        for (int i = 0; i < 8; i++) {
            int m = (i < 4) ? (ty*4 + i) : (64 + ty*4 + (i - 4));
            float invn = 1.0f / fmaxf(sqrtf(snorm[m]), 1e-12f);
            float best = FLT_MAX; int bc = 1 << 30;
            #pragma unroll
            for (int s = 0; s < 4; s++) {
                int j0 = 2*tx + 32*s;
                float sc0 = sen2[j0]   - 2.0f * invn * f2lo(acc[i][s]);
                float sc1 = sen2[j0+1] - 2.0f * invn * f2hi(acc[i][s]);
                if (sc0 < best || (sc0 == best && j0 < bc))   { best = sc0; bc = j0; }
                if (sc1 < best || (sc1 == best && j0+1 < bc)) { best = sc1; bc = j0+1; }
            }
            #pragma unroll
            for (int o = 8; o; o >>= 1) {
                float s2 = __shfl_xor_sync(0xffffffffu, best, o);
                int   c2 = __shfl_xor_sync(0xffffffffu, bc,   o);
                if (s2 < best || (s2 == best && c2 < bc)) { best = s2; bc = c2; }
            }
            if (tx == 0 && m < rows) {
                int tok  = toks[m];
                int code = type * PER + bc;
                scodes[m] = code;
                out[ND + 2 + tok] = (float)code;
                float e2 = sen2[bc];
                // ||q - xn||^2 = 2 - (e2 - best)/sqrt(e2)
                local_loss += 2.0f - (e2 - best) / sqrtf(e2);
            }
        }
        __syncthreads();

        // --- fused finalize: out row = g_ne[code] ---
        if (fr < rows) {
            const float4* src = (const float4*)(g_ne + (size_t)scodes[fr] * DIM) + fq * 64;
            float4*       dst = (float4*)(out + (size_t)toks[fr] * DIM) + fq * 64;
            #pragma unroll 8
            for (int q = 0; q < 64; q++) dst[q] = src[q];
        }
        // loop-top __syncthreads orders copy before smem reuse
    }

    red[tid] = local_loss;
    __syncthreads();
    for (int s = 128; s; s >>= 1) {
        if (tid < s) red[tid] += red[tid + s];
        __syncthreads();
    }
    if (tid == 0 && red[0] != 0.0f) atomicAdd(&g_diff_acc, (double)red[0]);
}

// block per sample row i; gathers rows straight from g_ne (no staging pass);
// last block writes scalar outputs.
__global__ __launch_bounds__(256) void k_uloss(const int* __restrict__ samp,
                                               float* __restrict__ out) {
    int i = blockIdx.x;
    __shared__ float si[DIM];
    __shared__ float wsum[8], wpos[8];
    int tid = threadIdx.x;
    int si_idx = samp[i];
    if (tid < 128)
        ((float4*)si)[tid] = ((const float4*)(g_ne + (size_t)si_idx * DIM))[tid];
    __syncthreads();
    int lab_i = si_idx / PER;
    int w = tid >> 5, lane = tid & 31;
    float sum = 0.0f, pos = 0.0f;
    for (int j = w; j < SAMP; j += 8) {
        int sj = samp[j];
        const float* vj = g_ne + (size_t)sj * DIM;
        float p = 0.0f;
        #pragma unroll 4
        for (int d = lane; d < DIM; d += 32) p = fmaf(si[d], vj[d], p);
        #pragma unroll
        for (int o = 16; o; o >>= 1) p += __shfl_xor_sync(0xffffffffu, p, o);
        if (lane == 0 && j != i) {
            float e = expf(p / TEMP);
            sum += e;
            if (sj / PER == lab_i) pos += e;
        }
    }
    if (lane == 0) { wsum[w] = sum; wpos[w] = pos; }
    __syncthreads();
    if (tid == 0) {
        float S = 0.0f, P = 0.0f;
        #pragma unroll
        for (int k = 0; k < 8; k++) { S += wsum[k]; P += wpos[k]; }
        atomicAdd(&g_uloss_acc, (double)(-logf(P / S)));
        __threadfence();
        int d = atomicAdd(&g_udone, 1);
        if (d == SAMP - 1) {
            double u = atomicAdd(&g_uloss_acc, 0.0);
            out[ND]     = (float)((1.0 + (double)COMMIT) * g_diff_acc / (double)ND);
            out[ND + 1] = (float)(u / (double)SAMP);
        }
    }
}

// -------- launch --------
extern "C" void kernel_launch(void* const* d_in, const int* in_sizes, int n_in,
                              void* d_out, int out_size) {
    const float* x    = (const float*)d_in[0];
    const float* emb  = (const float*)d_in[1];
    const int*   Q    = (const int*)d_in[2];
    const int*   samp = (const int*)d_in[3];
    float* out = (float*)d_out;

    k_init<<<1, 32>>>();
    k_norm_emb<<<NCODE, 128>>>(emb);
    k_hist<<<64, 256>>>(Q);
    k_scatter<<<64, 256>>>(Q);
    k_argmin<<<296, 256>>>(x, emb, out);
    k_uloss<<<SAMP, 256>>>(samp, out);
}